// round 17
// baseline (speedup 1.0000x reference)
#include <cuda_runtime.h>
#include <cuda_bf16.h>
#include <cstdint>

#define B_ 8
#define N_ 2048
#define F_ 128
#define M_ (B_*N_)
#define LAYERS_ 2
#define SLOPE_ 0.1f
#define INV_NM1_ (1.0f/2047.0f)
#define TE_ (F_*F_)

typedef unsigned long long ull;
typedef __nv_bfloat16 bf16;

// ---------------- scratch (device globals) ----------------
__device__ float g_diag[M_];
__device__ __align__(16) bf16 g_xh[M_*F_],  g_xl[M_*F_];
__device__ __align__(16) bf16 g_w1h[M_*F_], g_w1l[M_*F_];
__device__ __align__(16) bf16 g_w2h[M_*F_], g_w2l[M_*F_];
__device__ __align__(16) bf16 g_WBh[LAYERS_*3*TE_], g_WBl[LAYERS_*3*TE_];
__device__ __align__(16) bf16 g_Sh[B_*TE_], g_Sl[B_*TE_];

__device__ __forceinline__ float lrelu(float v){ return v>=0.f? v : SLOPE_*v; }
__device__ __forceinline__ void bsp(float v, bf16&h, bf16&l){
    h = __float2bfloat16(v); l = __float2bfloat16(v - __bfloat162float(h));
}
__device__ __forceinline__ uint32_t smem_u32(const void* p){
    uint32_t a; asm("{ .reg .u64 t; cvta.to.shared.u64 t, %1; cvt.u32.u64 %0, t; }" : "=r"(a) : "l"(p));
    return a;
}

// ---------------- MMA / ldmatrix / cp.async wrappers ----------------
__device__ __forceinline__ void ldsm4(uint32_t addr, uint32_t r[4]){
    asm volatile("ldmatrix.sync.aligned.m8n8.x4.shared.b16 {%0,%1,%2,%3}, [%4];"
        : "=r"(r[0]), "=r"(r[1]), "=r"(r[2]), "=r"(r[3]) : "r"(addr));
}
__device__ __forceinline__ void ldsm4t(uint32_t addr, uint32_t r[4]){
    asm volatile("ldmatrix.sync.aligned.m8n8.x4.trans.shared.b16 {%0,%1,%2,%3}, [%4];"
        : "=r"(r[0]), "=r"(r[1]), "=r"(r[2]), "=r"(r[3]) : "r"(addr));
}
__device__ __forceinline__ void mma16816(float d[4], const uint32_t a[4], const uint32_t b[2]){
    asm volatile("mma.sync.aligned.m16n8k16.row.col.f32.bf16.bf16.f32 "
        "{%0,%1,%2,%3}, {%4,%5,%6,%7}, {%8,%9}, {%0,%1,%2,%3};"
        : "+f"(d[0]), "+f"(d[1]), "+f"(d[2]), "+f"(d[3])
        : "r"(a[0]), "r"(a[1]), "r"(a[2]), "r"(a[3]), "r"(b[0]), "r"(b[1]));
}
__device__ __forceinline__ void cpa16(uint32_t dst, const void* src){
    asm volatile("cp.async.cg.shared.global [%0], [%1], 16;" :: "r"(dst), "l"(src));
}
#define CP_COMMIT() asm volatile("cp.async.commit_group;" ::: "memory")
#define CP_WAIT(n)  asm volatile("cp.async.wait_group %0;" :: "n"(n) : "memory")

// smem strides (bf16 elems)
#define SA_ 72      // A tiles (128x64), 144 B rows
#define SB_ 136     // B tiles (64x128), 272 B rows
#define SC_ 40      // k_S tiles (128x32), 80 B rows (16B-aligned)
#define ATB_ 18432
#define BTB_ 17408
#define CTB_ 10240  // 128 x SC_ x 2
// k_w1w2
#define W_BLK (2*ATB_ + 4*BTB_)
#define W_SMEM (2*W_BLK)                 // 212992
// k_S: per-chunk [AH][AL][BH][BL], double-buffered
#define SK_BLK (4*CTB_)                  // 40960
#define SK_SMEM (2*SK_BLK)               // 81920
// k_msg_out
#define G_RSZ 34816
#define G_BLK (2*ATB_ + 2*BTB_)
#define G_CH0 (2*G_RSZ)
#define G_SMEM (2*G_RSZ + 2*G_BLK)       // 212992

// ---------------------------------------------------------------------------
// async chunk loaders
__device__ __forceinline__ void ldA_a(uint32_t sdst, const bf16* g, int row0, int c, int tid){
    #pragma unroll
    for (int i = 0; i < 4; ++i) {
        int f4 = tid + i*256;
        int r = f4 >> 3, q = (f4 & 7)*8;
        cpa16(sdst + (uint32_t)(r*SA_ + q)*2, &g[(size_t)(row0 + r)*F_ + c*64 + q]);
    }
}
__device__ __forceinline__ void ldB_a(uint32_t sdst, const bf16* g, int c, int tid){
    #pragma unroll
    for (int i = 0; i < 4; ++i) {
        int f4 = tid + i*256;
        int r = f4 >> 4, q = (f4 & 15)*8;
        cpa16(sdst + (uint32_t)(r*SB_ + q)*2, &g[(size_t)(c*64 + r)*F_ + q]);
    }
}
// k_S tile: 128 k-rows x 32 cols at (rowBase, col0)
__device__ __forceinline__ void ldC_a(uint32_t sdst, const bf16* g, size_t rowBase, int col0, int tid){
    #pragma unroll
    for (int i = 0; i < 2; ++i) {
        int f4 = tid + i*256;
        int r = f4 >> 2, q = (f4 & 3)*8;
        cpa16(sdst + (uint32_t)(r*SC_ + q)*2, &g[(rowBase + r)*F_ + col0 + q]);
    }
}

// fragment address helpers
__device__ __forceinline__ uint32_t aAddr(uint32_t base, int stride, int row16, int kcol, int l){
    int row = row16 + (l & 7) + ((l >> 3) & 1)*8;
    int kc  = kcol + ((l >> 4) & 1)*8;
    return base + (uint32_t)(row*stride + kc)*2;
}
__device__ __forceinline__ uint32_t bAddr(uint32_t base, int stride, int krow, int ncol, int l){
    int kr = krow + (l & 7) + ((l >> 3) & 1)*8;
    int nc = ncol + ((l >> 4) & 1)*8;
    return base + (uint32_t)(kr*stride + nc)*2;
}
__device__ __forceinline__ uint32_t atAddr(uint32_t base, int stride, int krow, int fcol, int l){
    int kr = krow + (l & 7) + ((l >> 4) & 1)*8;
    int fc = fcol + ((l >> 3) & 1)*8;
    return base + (uint32_t)(kr*stride + fc)*2;
}

// ---------------------------------------------------------------------------
// prep kernels
__global__ void __launch_bounds__(256) k_splitX(const float4* __restrict__ X,
    bf16* __restrict__ xh, bf16* __restrict__ xl)
{
    int idx = blockIdx.x*256 + threadIdx.x;
    float4 v = X[idx];
    bf16 h[4], l[4];
    bsp(v.x,h[0],l[0]); bsp(v.y,h[1],l[1]); bsp(v.z,h[2],l[2]); bsp(v.w,h[3],l[3]);
    __nv_bfloat162 p0, p1;
    p0.x=h[0]; p0.y=h[1]; p1.x=h[2]; p1.y=h[3];
    uint2 u; u.x = *(uint32_t*)&p0; u.y = *(uint32_t*)&p1;
    *(uint2*)&xh[idx*4] = u;
    p0.x=l[0]; p0.y=l[1]; p1.x=l[2]; p1.y=l[3];
    u.x = *(uint32_t*)&p0; u.y = *(uint32_t*)&p1;
    *(uint2*)&xl[idx*4] = u;
}

__global__ void __launch_bounds__(256) k_prepW(
    const float* __restrict__ W3, const float* __restrict__ W4, const float* __restrict__ W5,
    bf16* __restrict__ wh, bf16* __restrict__ wl)
{
    int idx = blockIdx.x*256 + threadIdx.x;
    int m = idx >> 14, e = idx & 16383;
    int l = m / 3, w = m % 3;
    const float* W = (w==0 ? W3 : (w==1 ? W4 : W5)) + (size_t)l*TE_;
    bf16 h, lo; bsp(W[e], h, lo);
    wh[(size_t)m*TE_ + e] = h; wl[(size_t)m*TE_ + e] = lo;
}

// ---------------------------------------------------------------------------
// HMMA fused w1/w2/diag (unchanged from R15)
// ---------------------------------------------------------------------------
__global__ void __launch_bounds__(256) k_w1w2(
    const bf16* __restrict__ xh, const bf16* __restrict__ xl,
    const bf16* __restrict__ w3h, const bf16* __restrict__ w3l,
    const bf16* __restrict__ w4h, const bf16* __restrict__ w4l,
    const float* __restrict__ b3, const float* __restrict__ b4,
    bf16* __restrict__ w2h, bf16* __restrict__ w2l,
    bf16* __restrict__ w1h, bf16* __restrict__ w1l,
    float* __restrict__ diag)
{
    extern __shared__ char sm[];
    __shared__ float dsh[256];
    const int tid = threadIdx.x, wid = tid>>5, l = tid&31;
    const int row0 = blockIdx.x * 128;
    const int mrow0 = (wid & 3)*32, ncol0 = (wid >> 2)*64;
    const uint32_t sb = smem_u32(sm);

    #pragma unroll
    for (int c = 0; c < 2; ++c) {
        uint32_t base = sb + c*W_BLK;
        ldA_a(base,            xh,  row0, c, tid);
        ldA_a(base + ATB_,     xl,  row0, c, tid);
        ldB_a(base + 2*ATB_,           w3h, c, tid);
        ldB_a(base + 2*ATB_ + BTB_,    w3l, c, tid);
        ldB_a(base + 2*ATB_ + 2*BTB_,  w4h, c, tid);
        ldB_a(base + 2*ATB_ + 3*BTB_,  w4l, c, tid);
        CP_COMMIT();
    }

    float acc3[2][8][4], acc4[2][8][4];
    #pragma unroll
    for (int mt = 0; mt < 2; ++mt)
        #pragma unroll
        for (int n = 0; n < 8; ++n)
            #pragma unroll
            for (int q = 0; q < 4; ++q) { acc3[mt][n][q] = 0.f; acc4[mt][n][q] = 0.f; }

    #pragma unroll
    for (int c = 0; c < 2; ++c) {
        if (c == 0) CP_WAIT(1); else CP_WAIT(0);
        __syncthreads();
        uint32_t base = sb + c*W_BLK;
        uint32_t AH = base, AL = base + ATB_;
        uint32_t B3H = base + 2*ATB_, B3L = B3H + BTB_, B4H = B3L + BTB_, B4L = B4H + BTB_;
        #pragma unroll
        for (int kk = 0; kk < 4; ++kk) {
            uint32_t ah[2][4], al_[2][4];
            #pragma unroll
            for (int mt = 0; mt < 2; ++mt) {
                ldsm4(aAddr(AH, SA_, mrow0 + mt*16, kk*16, l), ah[mt]);
                ldsm4(aAddr(AL, SA_, mrow0 + mt*16, kk*16, l), al_[mt]);
            }
            #pragma unroll
            for (int np = 0; np < 4; ++np) {
                uint32_t b3hF[4], b3lF[4], b4hF[4], b4lF[4];
                ldsm4t(bAddr(B3H, SB_, kk*16, ncol0 + np*16, l), b3hF);
                ldsm4t(bAddr(B3L, SB_, kk*16, ncol0 + np*16, l), b3lF);
                ldsm4t(bAddr(B4H, SB_, kk*16, ncol0 + np*16, l), b4hF);
                ldsm4t(bAddr(B4L, SB_, kk*16, ncol0 + np*16, l), b4lF);
                #pragma unroll
                for (int mt = 0; mt < 2; ++mt) {
                    #pragma unroll
                    for (int hnf = 0; hnf < 2; ++hnf) {
                        int n = np*2 + hnf;
                        mma16816(acc3[mt][n], ah[mt],  &b3hF[hnf*2]);
                        mma16816(acc3[mt][n], ah[mt],  &b3lF[hnf*2]);
                        mma16816(acc3[mt][n], al_[mt], &b3hF[hnf*2]);
                        mma16816(acc4[mt][n], ah[mt],  &b4hF[hnf*2]);
                        mma16816(acc4[mt][n], ah[mt],  &b4lF[hnf*2]);
                        mma16816(acc4[mt][n], al_[mt], &b4hF[hnf*2]);
                    }
                }
            }
        }
    }

    float dp[2][2] = {{0.f,0.f},{0.f,0.f}};
    #pragma unroll
    for (int mt = 0; mt < 2; ++mt) {
        #pragma unroll
        for (int n = 0; n < 8; ++n) {
            int col = ncol0 + n*8 + (l & 3)*2;
            float bb3a = b3[col], bb3b = b3[col+1];
            float bb4a = b4[col], bb4b = b4[col+1];
            #pragma unroll
            for (int hf = 0; hf < 2; ++hf) {
                int row = mrow0 + mt*16 + (l >> 2) + hf*8;
                float v1a = lrelu(acc3[mt][n][hf*2+0] + bb3a);
                float v1b = lrelu(acc3[mt][n][hf*2+1] + bb3b);
                float v2a = lrelu(acc4[mt][n][hf*2+0] + bb4a);
                float v2b = lrelu(acc4[mt][n][hf*2+1] + bb4b);
                dp[mt][hf] += v1a*v2a + v1b*v2b;
                size_t gg = (size_t)(row0 + row)*F_ + col;
                bf16 h0,l0,h1,l1;
                bsp(v1a,h0,l0); bsp(v1b,h1,l1);
                __nv_bfloat162 p;
                p.x=h0; p.y=h1; *(__nv_bfloat162*)&w1h[gg] = p;
                p.x=l0; p.y=l1; *(__nv_bfloat162*)&w1l[gg] = p;
                bsp(v2a,h0,l0); bsp(v2b,h1,l1);
                p.x=h0; p.y=h1; *(__nv_bfloat162*)&w2h[gg] = p;
                p.x=l0; p.y=l1; *(__nv_bfloat162*)&w2l[gg] = p;
            }
        }
    }
    #pragma unroll
    for (int mt = 0; mt < 2; ++mt)
        #pragma unroll
        for (int hf = 0; hf < 2; ++hf) {
            float d = dp[mt][hf];
            d += __shfl_xor_sync(0xffffffffu, d, 1);
            d += __shfl_xor_sync(0xffffffffu, d, 2);
            if ((l & 3) == 0) {
                int row = mrow0 + mt*16 + (l >> 2) + hf*8;
                dsh[(wid >> 2)*128 + row] = d;
            }
        }
    __syncthreads();
    if (tid < 128) diag[row0 + tid] = dsh[tid] + dsh[128 + tid];
}

// ---------------------------------------------------------------------------
// k_S: output-partitioned S[b] = w2[b]^T @ x[b], full K=2048 per block.
// grid (16, B_): blockIdx.x = fb*4 + gb; each block -> 32x32 output tile.
// 8 warps split each 128-k chunk by k (16 rows each); fixed-order smem reduce.
// Emits Sh/Sl bf16 directly. No split-K scratch.
// ---------------------------------------------------------------------------
__global__ void __launch_bounds__(256) k_S(
    const bf16* __restrict__ w2h, const bf16* __restrict__ w2l,
    const bf16* __restrict__ xh,  const bf16* __restrict__ xl,
    bf16* __restrict__ sh, bf16* __restrict__ sl)
{
    extern __shared__ char sm[];
    const int tid = threadIdx.x, wid = tid>>5, l = tid&31;
    const int b = blockIdx.y;
    const int fb = blockIdx.x >> 2, gb = blockIdx.x & 3;
    const uint32_t sb = smem_u32(sm);
    const size_t baseRow = (size_t)b*N_;

    // prefetch chunks 0,1
    #pragma unroll
    for (int c = 0; c < 2; ++c) {
        uint32_t base = sb + c*SK_BLK;
        size_t rb = baseRow + c*128;
        ldC_a(base,          w2h, rb, fb*32, tid);
        ldC_a(base + CTB_,   w2l, rb, fb*32, tid);
        ldC_a(base + 2*CTB_, xh,  rb, gb*32, tid);
        ldC_a(base + 3*CTB_, xl,  rb, gb*32, tid);
        CP_COMMIT();
    }

    float acc[2][4][4];
    #pragma unroll
    for (int mt = 0; mt < 2; ++mt)
        #pragma unroll
        for (int nf = 0; nf < 4; ++nf)
            #pragma unroll
            for (int q = 0; q < 4; ++q) acc[mt][nf][q] = 0.f;

    const int krow = wid*16;
    for (int ch = 0; ch < 16; ++ch) {
        CP_WAIT(1);
        __syncthreads();
        uint32_t base = sb + (ch & 1)*SK_BLK;
        uint32_t AH = base, AL = base + CTB_, BH = base + 2*CTB_, BL = base + 3*CTB_;

        uint32_t ah[2][4], al_[2][4], bh0[4], bh1[4], bl0[4], bl1[4];
        ldsm4t(atAddr(AH, SC_, krow, 0,  l), ah[0]);
        ldsm4t(atAddr(AH, SC_, krow, 16, l), ah[1]);
        ldsm4t(atAddr(AL, SC_, krow, 0,  l), al_[0]);
        ldsm4t(atAddr(AL, SC_, krow, 16, l), al_[1]);
        ldsm4t(bAddr(BH, SC_, krow, 0,  l), bh0);
        ldsm4t(bAddr(BH, SC_, krow, 16, l), bh1);
        ldsm4t(bAddr(BL, SC_, krow, 0,  l), bl0);
        ldsm4t(bAddr(BL, SC_, krow, 16, l), bl1);

        #pragma unroll
        for (int mt = 0; mt < 2; ++mt) {
            #pragma unroll
            for (int nf = 0; nf < 4; ++nf) {
                const uint32_t* bh = (nf < 2) ? &bh0[(nf & 1)*2] : &bh1[(nf & 1)*2];
                const uint32_t* bl = (nf < 2) ? &bl0[(nf & 1)*2] : &bl1[(nf & 1)*2];
                mma16816(acc[mt][nf], ah[mt],  bh);
                mma16816(acc[mt][nf], ah[mt],  bl);
                mma16816(acc[mt][nf], al_[mt], bh);
            }
        }
        __syncthreads();
        if (ch + 2 < 16) {
            uint32_t dst = sb + (ch & 1)*SK_BLK;
            size_t rb = baseRow + (size_t)(ch + 2)*128;
            ldC_a(dst,          w2h, rb, fb*32, tid);
            ldC_a(dst + CTB_,   w2l, rb, fb*32, tid);
            ldC_a(dst + 2*CTB_, xh,  rb, gb*32, tid);
            ldC_a(dst + 3*CTB_, xl,  rb, gb*32, tid);
            CP_COMMIT();
        }
    }

    // fixed-order cross-warp reduction in smem (reuse chunk buffers)
    float* rbuf = (float*)sm;   // 8 warps x 1024 f32 = 32 KB
    #pragma unroll
    for (int mt = 0; mt < 2; ++mt) {
        #pragma unroll
        for (int nf = 0; nf < 4; ++nf) {
            int col = nf*8 + (l & 3)*2;
            #pragma unroll
            for (int hf = 0; hf < 2; ++hf) {
                int row = mt*16 + (l >> 2) + hf*8;
                rbuf[wid*1024 + row*32 + col]     = acc[mt][nf][hf*2+0];
                rbuf[wid*1024 + row*32 + col + 1] = acc[mt][nf][hf*2+1];
            }
        }
    }
    __syncthreads();
    #pragma unroll
    for (int j = 0; j < 4; ++j) {
        int e = tid + j*256;             // 0..1023
        float s = 0.f;
        #pragma unroll
        for (int w = 0; w < 8; ++w) s += rbuf[w*1024 + e];
        int f = e >> 5, g = e & 31;
        bf16 h, lo; bsp(s, h, lo);
        size_t idx = (size_t)b*TE_ + (size_t)(fb*32 + f)*F_ + gb*32 + g;
        sh[idx] = h; sl[idx] = lo;
    }
}

// ---------------------------------------------------------------------------
// HMMA fused msg+out (unchanged from R15)
// ---------------------------------------------------------------------------
__global__ void __launch_bounds__(256) k_msg_out(
    const bf16* __restrict__ w1h, const bf16* __restrict__ w1l,
    const float* __restrict__ diag, const float* __restrict__ x,
    const bf16* __restrict__ sh, const bf16* __restrict__ sl,
    const bf16* __restrict__ w5h, const bf16* __restrict__ w5l,
    const float* __restrict__ b5,
    float* __restrict__ out, bf16* __restrict__ nxh, bf16* __restrict__ nxl)
{
    extern __shared__ char sm[];
    __shared__ float ds[128];
    const int tid = threadIdx.x, wid = tid>>5, l = tid&31;
    const int row0 = blockIdx.x * 128, b = blockIdx.x >> 4;
    const int mrow0 = (wid & 3)*32, ncol0 = (wid >> 2)*64;
    const uint32_t sb = smem_u32(sm);

    #pragma unroll
    for (int c = 0; c < 2; ++c) {
        uint32_t base = sb + G_CH0 + c*G_BLK;
        ldA_a(base,          w1h, row0, c, tid);
        ldA_a(base + ATB_,   w1l, row0, c, tid);
        ldB_a(base + 2*ATB_,        sh + (size_t)b*TE_, c, tid);
        ldB_a(base + 2*ATB_ + BTB_, sl + (size_t)b*TE_, c, tid);
        CP_COMMIT();
    }
    if (tid < 128) ds[tid] = diag[row0 + tid];

    float acc[2][8][4];
    #pragma unroll
    for (int mt = 0; mt < 2; ++mt)
        #pragma unroll
        for (int n = 0; n < 8; ++n)
            #pragma unroll
            for (int q = 0; q < 4; ++q) acc[mt][n][q] = 0.f;

    #pragma unroll
    for (int c = 0; c < 2; ++c) {
        if (c == 0) CP_WAIT(1); else CP_WAIT(0);
        __syncthreads();
        uint32_t base = sb + G_CH0 + c*G_BLK;
        uint32_t AH = base, AL = base + ATB_, BH = base + 2*ATB_, BL = BH + BTB_;
        #pragma unroll
        for (int kk = 0; kk < 4; ++kk) {
            uint32_t ah[2][4], al_[2][4];
            #pragma unroll
            for (int mt = 0; mt < 2; ++mt) {
                ldsm4(aAddr(AH, SA_, mrow0 + mt*16, kk*16, l), ah[mt]);
                ldsm4(aAddr(AL, SA_, mrow0 + mt*16, kk*16, l), al_[mt]);
            }
            #pragma unroll
            for (int np = 0; np < 4; ++np) {
                uint32_t bhF[4], blF[4];
                ldsm4t(bAddr(BH, SB_, kk*16, ncol0 + np*16, l), bhF);
                ldsm4t(bAddr(BL, SB_, kk*16, ncol0 + np*16, l), blF);
                #pragma unroll
                for (int mt = 0; mt < 2; ++mt) {
                    #pragma unroll
                    for (int hnf = 0; hnf < 2; ++hnf) {
                        int n = np*2 + hnf;
                        mma16816(acc[mt][n], ah[mt],  &bhF[hnf*2]);
                        mma16816(acc[mt][n], ah[mt],  &blF[hnf*2]);
                        mma16816(acc[mt][n], al_[mt], &bhF[hnf*2]);
                    }
                }
            }
        }
    }
    __syncthreads();

    #pragma unroll
    for (int c = 0; c < 2; ++c) {
        uint32_t base = sb + G_CH0 + c*G_BLK;
        ldB_a(base + 2*ATB_,        w5h, c, tid);
        ldB_a(base + 2*ATB_ + BTB_, w5l, c, tid);
        CP_COMMIT();
    }

    {
        bf16* mh = (bf16*)(sm);
        bf16* ml = (bf16*)(sm + G_RSZ);
        #pragma unroll
        for (int mt = 0; mt < 2; ++mt) {
            #pragma unroll
            for (int hf = 0; hf < 2; ++hf) {
                int row = mrow0 + mt*16 + (l >> 2) + hf*8;
                float dv = ds[row];
                size_t gg = (size_t)(row0 + row)*F_;
                #pragma unroll
                for (int n = 0; n < 8; ++n) {
                    int col = ncol0 + n*8 + (l & 3)*2;
                    float2 xv = *(const float2*)&x[gg + col];
                    float a0 = (acc[mt][n][hf*2+0] - dv*xv.x) * INV_NM1_;
                    float a1 = (acc[mt][n][hf*2+1] - dv*xv.y) * INV_NM1_;
                    bf16 h0,l0,h1,l1; bsp(a0,h0,l0); bsp(a1,h1,l1);
                    __nv_bfloat162 p;
                    p.x=h0; p.y=h1; *(__nv_bfloat162*)&mh[row*SB_ + col] = p;
                    p.x=l0; p.y=l1; *(__nv_bfloat162*)&ml[row*SB_ + col] = p;
                }
            }
        }
    }
    CP_WAIT(0);
    __syncthreads();

    #pragma unroll
    for (int mt = 0; mt < 2; ++mt)
        #pragma unroll
        for (int n = 0; n < 8; ++n)
            #pragma unroll
            for (int q = 0; q < 4; ++q) acc[mt][n][q] = 0.f;

    #pragma unroll
    for (int c = 0; c < 2; ++c) {
        uint32_t base = sb + G_CH0 + c*G_BLK;
        uint32_t BH = base + 2*ATB_, BL = BH + BTB_;
        #pragma unroll
        for (int kk = 0; kk < 4; ++kk) {
            uint32_t ah[2][4], al_[2][4];
            #pragma unroll
            for (int mt = 0; mt < 2; ++mt) {
                ldsm4(aAddr(sb,         SB_, mrow0 + mt*16, c*64 + kk*16, l), ah[mt]);
                ldsm4(aAddr(sb + G_RSZ, SB_, mrow0 + mt*16, c*64 + kk*16, l), al_[mt]);
            }
            #pragma unroll
            for (int np = 0; np < 4; ++np) {
                uint32_t bhF[4], blF[4];
                ldsm4t(bAddr(BH, SB_, kk*16, ncol0 + np*16, l), bhF);
                ldsm4t(bAddr(BL, SB_, kk*16, ncol0 + np*16, l), blF);
                #pragma unroll
                for (int mt = 0; mt < 2; ++mt) {
                    #pragma unroll
                    for (int hnf = 0; hnf < 2; ++hnf) {
                        int n = np*2 + hnf;
                        mma16816(acc[mt][n], ah[mt],  &bhF[hnf*2]);
                        mma16816(acc[mt][n], ah[mt],  &blF[hnf*2]);
                        mma16816(acc[mt][n], al_[mt], &bhF[hnf*2]);
                    }
                }
            }
        }
    }

    #pragma unroll
    for (int mt = 0; mt < 2; ++mt) {
        #pragma unroll
        for (int n = 0; n < 8; ++n) {
            int col = ncol0 + n*8 + (l & 3)*2;
            float ba = b5[col], bb = b5[col+1];
            #pragma unroll
            for (int hf = 0; hf < 2; ++hf) {
                int row = mrow0 + mt*16 + (l >> 2) + hf*8;
                size_t gg = (size_t)(row0 + row)*F_ + col;
                float2 xv = *(const float2*)&x[gg];
                float v0 = lrelu(acc[mt][n][hf*2+0] + ba) + xv.x;
                float v1 = lrelu(acc[mt][n][hf*2+1] + bb) + xv.y;
                float2 ov; ov.x = v0; ov.y = v1;
                *(float2*)&out[gg] = ov;
                bf16 h0,l0,h1,l1; bsp(v0,h0,l0); bsp(v1,h1,l1);
                __nv_bfloat162 p;
                p.x=h0; p.y=h1; *(__nv_bfloat162*)&nxh[gg] = p;
                p.x=l0; p.y=l1; *(__nv_bfloat162*)&nxl[gg] = p;
            }
        }
    }
}

// ---------------------------------------------------------------------------
extern "C" void kernel_launch(void* const* d_in, const int* in_sizes, int n_in,
                              void* d_out, int out_size)
{
    const float* x  = (const float*)d_in[0];
    const float* W3 = (const float*)d_in[1];
    const float* b3 = (const float*)d_in[2];
    const float* W4 = (const float*)d_in[3];
    const float* b4 = (const float*)d_in[4];
    const float* W5 = (const float*)d_in[5];
    const float* b5 = (const float*)d_in[6];
    float* out = (float*)d_out;

    cudaFuncSetAttribute(k_w1w2,    cudaFuncAttributeMaxDynamicSharedMemorySize, W_SMEM);
    cudaFuncSetAttribute(k_msg_out, cudaFuncAttributeMaxDynamicSharedMemorySize, G_SMEM);
    cudaFuncSetAttribute(k_S,       cudaFuncAttributeMaxDynamicSharedMemorySize, SK_SMEM);

    float *pdg;
    bf16 *pxh, *pxl, *pw1h, *pw1l, *pw2h, *pw2l, *pWh, *pWl, *pSh, *pSl;
    cudaGetSymbolAddress((void**)&pdg,  g_diag);
    cudaGetSymbolAddress((void**)&pxh,  g_xh);
    cudaGetSymbolAddress((void**)&pxl,  g_xl);
    cudaGetSymbolAddress((void**)&pw1h, g_w1h);
    cudaGetSymbolAddress((void**)&pw1l, g_w1l);
    cudaGetSymbolAddress((void**)&pw2h, g_w2h);
    cudaGetSymbolAddress((void**)&pw2l, g_w2l);
    cudaGetSymbolAddress((void**)&pWh,  g_WBh);
    cudaGetSymbolAddress((void**)&pWl,  g_WBl);
    cudaGetSymbolAddress((void**)&pSh,  g_Sh);
    cudaGetSymbolAddress((void**)&pSl,  g_Sl);

    k_splitX<<<(M_*F_/4)/256, 256>>>((const float4*)x, pxh, pxl);
    k_prepW<<<(6*TE_)/256, 256>>>(W3, W4, W5, pWh, pWl);

    for (int l = 0; l < LAYERS_; ++l) {
        const float* xinF = l ? out : x;
        const bf16* Wh = pWh + (size_t)l*3*TE_;
        const bf16* Wl = pWl + (size_t)l*3*TE_;

        k_w1w2<<<M_/128, 256, W_SMEM>>>(pxh, pxl,
                                        Wh, Wl, Wh + TE_, Wl + TE_,
                                        b3 + l*F_, b4 + l*F_,
                                        pw2h, pw2l, pw1h, pw1l, pdg);
        k_S<<<dim3(16, B_), 256, SK_SMEM>>>(pw2h, pw2l, pxh, pxl, pSh, pSl);
        k_msg_out<<<M_/128, 256, G_SMEM>>>(pw1h, pw1l, pdg, xinF,
                                           pSh, pSl,
                                           Wh + 2*TE_, Wl + 2*TE_,
                                           b5 + l*F_, out, pxh, pxl);
    }
}